// round 13
// baseline (speedup 1.0000x reference)
#include <cuda_runtime.h>

#define BDIM  256
#define CHUNK 4096
#define E     16          // outputs per thread (CHUNK/BDIM)
#define NLEN  131072
#define GT    33          // composed tap count
#define NPAIR 24          // aligned window pairs A_0..A_23  (w[48])

// padded smem layout: 4 floats of pad per 16 floats -> per-lane window stride
// 80B, (i*80) mod 128 covers all 8 bank quads => conflict-free LDS.128
#define PHYS(idx) ((idx) + (((idx) >> 4) << 2))
#define XS_LOG   (CHUNK + 32)                    // 4128 logical floats
#define XS_PHYS  (XS_LOG + (XS_LOG / 16) * 4)

typedef unsigned long long u64;

__device__ __forceinline__ u64 ffma2(u64 a, u64 b, u64 c) {
    u64 d;
    asm("fma.rn.f32x2 %0, %1, %2, %3;" : "=l"(d) : "l"(a), "l"(b), "l"(c));
    return d;
}
__device__ __forceinline__ float2 unpk(u64 v) {
    float2 r;
    asm("mov.b64 {%0, %1}, %2;" : "=f"(r.x), "=f"(r.y) : "l"(v));
    return r;
}

__global__ __launch_bounds__(BDIM, 2)
void fir2p_kernel(const float* __restrict__ x,
                  const float* __restrict__ kern,
                  float* __restrict__ out) {
    __shared__ __align__(16) float xs[XS_PHYS];      // padded x tile
    __shared__ __align__(8)  float ge2[2 * 17];      // even taps g[2m], duplicated
    __shared__ __align__(8)  float go2[2 * 16];      // odd  taps g[2m+1], duplicated
    __shared__ float hsm[16];

    const int tid = threadIdx.x;
    const int row = blockIdx.y;
    const int chunkStart = blockIdx.x * CHUNK;
    const float* xrow = x + (size_t)row * NLEN;
    float* orow = out + (size_t)row * NLEN;

    if (tid < 16) hsm[tid] = kern[tid];

    // ---- cooperative vectorized load of x tile + 32-left halo (padded STS) ----
    {
        const int gbase = chunkStart - 32;
        #pragma unroll
        for (int i = tid; i < XS_LOG / 4; i += BDIM) {
            int idx = 4 * i;                       // logical float index, quad-aligned
            int g = gbase + idx;                   // whole quad in/out of range
            float4 v = make_float4(0.f, 0.f, 0.f, 0.f);
            if (g >= 0) v = *(const float4*)(xrow + g);
            *(float4*)&xs[PHYS(idx)] = v;
        }
    }
    __syncthreads();   // hsm + xs visible

    // ---- compose g = (delta + hr) * (delta + h), split into polyphases ----
    if (tid < GT) {
        float acc = (tid == 0) ? 1.f : 0.f;
        if (tid >= 1 && tid <= 16) acc += hsm[tid - 1] + hsm[16 - tid];
        int mlo = (tid - 16 > 1) ? tid - 16 : 1;
        int mhi = (tid - 1 < 16) ? tid - 1 : 16;
        for (int m = mlo; m <= mhi; m++)
            acc += hsm[m - 1] * hsm[16 - (tid - m)];
        if ((tid & 1) == 0) { ge2[tid] = acc;     ge2[tid + 1] = acc; }     // ge2[2*(tid/2)]
        else                { go2[tid - 1] = acc; go2[tid] = acc; }          // go2[2*(tid/2)]
    }
    __syncthreads();

    const int base = tid * E;                       // local output base
    const bool fixup = (chunkStart == 0) && (tid < 2);

    if (!fixup) {
        // window w[j] = xs_log[base + j], j in [0,48); aligned pairs A_k = w64[k]
        __align__(16) float w[48];
        #pragma unroll
        for (int q = 0; q < 12; q++) {
            const int idx = base + 4 * q;          // quad never straddles a pad boundary
            ((float4*)w)[q] = *(const float4*)&xs[PHYS(idx)];
        }
        const u64* A = (const u64*)w;              // A_0..A_23

        // EvenAcc_i  (i = pair index 0..7):  Ev[i] = sum_m ge[m] * A[i+16-m]
        // OddAcc_{15+t} (t = 0..8):          Od[t] = sum_m go[m] * A[15+t-m]
        u64 Ev[8], Od[9];
        #pragma unroll
        for (int i = 0; i < 8; i++) Ev[i] = 0ull;
        #pragma unroll
        for (int t = 0; t < 9; t++) Od[t] = 0ull;

        #pragma unroll
        for (int m = 0; m < 17; m++) {
            u64 gg = *(const u64*)(ge2 + 2 * m);   // LDS.64 broadcast (ge,ge)
            #pragma unroll
            for (int i = 0; i < 8; i++)
                Ev[i] = ffma2(gg, A[i + 16 - m], Ev[i]);
        }
        #pragma unroll
        for (int m = 0; m < 16; m++) {
            u64 gg = *(const u64*)(go2 + 2 * m);   // LDS.64 broadcast (go,go)
            #pragma unroll
            for (int t = 0; t < 9; t++)
                Od[t] = ffma2(gg, A[15 + t - m], Od[t]);
        }

        // recombine: y[base+2i]   = Ev[i].lo + hi(OddAcc_{i+15})
        //            y[base+2i+1] = Ev[i].hi + lo(OddAcc_{i+16})
        #pragma unroll
        for (int i = 0; i < 8; i += 2) {
            float2 e0 = unpk(Ev[i]);
            float2 oA = unpk(Od[i]);
            float2 oB = unpk(Od[i + 1]);
            float2 e1 = unpk(Ev[i + 1]);
            float2 oC = unpk(Od[i + 2]);
            float4 r;
            r.x = e0.x + oA.y;
            r.y = e0.y + oB.x;
            r.z = e1.x + oB.y;
            r.w = e1.y + oC.x;
            *(float4*)(orow + chunkStart + base + 2 * i) = r;
        }
    } else {
        // chunkStart == 0: outputs [0,32); the intermediate mask matters here.
        if (tid == 0) {
            // y[0..15] = 0
            #pragma unroll
            for (int q = 0; q < 4; q++)
                *(float4*)(orow + 4 * q) = make_float4(0.f, 0.f, 0.f, 0.f);
        } else {
            // exact two-stage for y[16..31]; needs x[0..31] = xs_log[32..63]
            float h[16];
            #pragma unroll
            for (int j = 0; j < 16; j++) h[j] = hsm[j];
            float xv[32];
            #pragma unroll
            for (int t = 0; t < 32; t++) {
                const int idx = 32 + t;
                xv[t] = xs[PHYS(idx)];
            }

            float u[16];                            // u[m] = v[16+m]
            #pragma unroll
            for (int m = 0; m < 16; m++) {
                float a = xv[16 + m];
                #pragma unroll
                for (int j = 0; j < 16; j++)
                    a = fmaf(h[j], xv[15 + m - j], a);
                u[m] = a;
            }
            #pragma unroll
            for (int o = 0; o < 16; o++) {
                float a = u[o];                     // v[16+o]
                for (int j = 0; j < o; j++)         // only v>=16 terms survive mask
                    a = fmaf(h[15 - j], u[o - j - 1], a);
                orow[16 + o] = a;
            }
        }
    }
}

extern "C" void kernel_launch(void* const* d_in, const int* in_sizes, int n_in,
                              void* d_out, int out_size) {
    const float* x    = (const float*)d_in[0];   // (256, 131072) f32
    const float* kern = (const float*)d_in[1];   // (1, 16) f32
    float* out        = (float*)d_out;

    dim3 grid(NLEN / CHUNK, 256, 1);             // 32 x 256 = 8192 CTAs
    fir2p_kernel<<<grid, BDIM>>>(x, kern, out);
}

// round 17
// speedup vs baseline: 1.2785x; 1.2785x over previous
#include <cuda_runtime.h>

#define BDIM  256
#define CHUNK 2048
#define E     8           // outputs per thread (CHUNK/BDIM)
#define NLEN  131072
#define GT    33          // composed tap count

// padding for 32B per-lane window stride: 4 floats pad per 8 floats.
// phys stride 48B; 48*i mod 128 = {0,48,96,16,64,112,32,80} -> all 8 bank
// quads distinct across an 8-lane LDS.128 phase => conflict-free.
// quads (idx%4==0) never straddle a pad boundary.
#define PHYS8(idx) ((idx) + (((idx) >> 3) << 2))
#define XS_LOG   (CHUNK + 32)                    // 2080 logical floats
#define XS_PHYS  (XS_LOG + (XS_LOG / 8) * 4)     // 3120 floats = 12480 B

__global__ __launch_bounds__(BDIM)
void fir2s_kernel(const float* __restrict__ x,
                  const float* __restrict__ kern,
                  float* __restrict__ out) {
    __shared__ __align__(16) float xs[XS_PHYS];  // padded x tile
    __shared__ float gs[GT];                     // composed taps
    __shared__ float hsm[16];

    const int tid = threadIdx.x;
    const int row = blockIdx.y;
    const int chunkStart = blockIdx.x * CHUNK;
    const float* xrow = x + (size_t)row * NLEN;
    float* orow = out + (size_t)row * NLEN;

    if (tid < 16) hsm[tid] = kern[tid];

    // ---- cooperative vectorized load of x tile + 32-left halo (padded STS) ----
    {
        const int gbase = chunkStart - 32;
        #pragma unroll
        for (int i = tid; i < XS_LOG / 4; i += BDIM) {
            int idx = 4 * i;                     // logical float index, quad-aligned
            int g = gbase + idx;                 // whole quad in/out of range
            float4 v = make_float4(0.f, 0.f, 0.f, 0.f);
            if (g >= 0) v = *(const float4*)(xrow + g);
            *(float4*)&xs[PHYS8(idx)] = v;
        }
    }
    __syncthreads();   // hsm + xs visible

    // ---- compose g = (delta + hr) * (delta + h): 33 taps ----
    if (tid < GT) {
        float acc = (tid == 0) ? 1.f : 0.f;
        if (tid >= 1 && tid <= 16) acc += hsm[tid - 1] + hsm[16 - tid];
        int mlo = (tid - 16 > 1) ? tid - 16 : 1;
        int mhi = (tid - 1 < 16) ? tid - 1 : 16;
        for (int m = mlo; m <= mhi; m++)
            acc += hsm[m - 1] * hsm[16 - (tid - m)];
        gs[tid] = acc;
    }
    __syncthreads();

    const int base = tid * E;                    // local output base
    const bool fixup = (chunkStart == 0) && (tid < 4);

    if (!fixup) {
        // window w[j] = xs_log[base + j] = x[chunkStart + base - 32 + j], j in [0,40)
        float w[40];
        #pragma unroll
        for (int q = 0; q < 10; q++) {
            const int idx = base + 4 * q;
            ((float4*)w)[q] = *(const float4*)&xs[PHYS8(idx)];
        }

        float acc[E];
        #pragma unroll
        for (int e = 0; e < E; e++) acc[e] = 0.f;

        // y[base+o] = sum_d gs[d] * w[o + 32 - d]
        #pragma unroll
        for (int d = 0; d < GT; d++) {
            const float g = gs[d];               // LDS broadcast, conflict-free
            #pragma unroll
            for (int e = 0; e < E; e++)
                acc[e] = fmaf(g, w[e + 32 - d], acc[e]);
        }

        #pragma unroll
        for (int q = 0; q < 2; q++)
            *(float4*)(orow + chunkStart + base + 4 * q) = ((float4*)&acc[4 * q])[0];
    } else {
        // chunkStart == 0: outputs [0,32); intermediate mask matters here.
        if (tid == 0 || tid == 1) {
            // y[0..15] = 0
            #pragma unroll
            for (int q = 0; q < 2; q++)
                *(float4*)(orow + tid * E + 4 * q) = make_float4(0.f, 0.f, 0.f, 0.f);
        } else if (tid == 2) {
            // exact two-stage for y[16..31]; needs x[0..31] = xs_log[32..63]
            float h[16];
            #pragma unroll
            for (int j = 0; j < 16; j++) h[j] = hsm[j];
            float xv[32];
            #pragma unroll
            for (int t = 0; t < 32; t++)
                xv[t] = xs[PHYS8(32 + t)];

            float u[16];                         // u[m] = v[16+m]
            #pragma unroll
            for (int m = 0; m < 16; m++) {
                float a = xv[16 + m];
                #pragma unroll
                for (int j = 0; j < 16; j++)
                    a = fmaf(h[j], xv[15 + m - j], a);
                u[m] = a;
            }
            #pragma unroll
            for (int o = 0; o < 16; o++) {
                float a = u[o];                  // v[16+o]
                for (int j = 0; j < o; j++)      // only v>=16 terms survive mask
                    a = fmaf(h[15 - j], u[o - j - 1], a);
                orow[16 + o] = a;
            }
        }
        // tid == 3: covered by tid 2
    }
}

extern "C" void kernel_launch(void* const* d_in, const int* in_sizes, int n_in,
                              void* d_out, int out_size) {
    const float* x    = (const float*)d_in[0];   // (256, 131072) f32
    const float* kern = (const float*)d_in[1];   // (1, 16) f32
    float* out        = (float*)d_out;

    dim3 grid(NLEN / CHUNK, 256, 1);             // 64 x 256 = 16384 CTAs
    fir2s_kernel<<<grid, BDIM>>>(x, kern, out);
}